// round 14
// baseline (speedup 1.0000x reference)
#include <cuda_runtime.h>

#define TK_D        16384
#define TK_THREADS  256
#define TK_NWARP    8                        // warps per CTA
#define TK_CHUNK    (TK_THREADS * 4)         // block-wide fallback scans
#define TK_NITER    (TK_D / TK_CHUNK)        // 16
#define TK_CAP      512                      // block fallback pool cap
#define TK_WCAP     256                      // per-warp pool cap (~+10 sigma)
#define TK_MAXROWS  8192

// Compact winner exchange: (ordered_key << 32) | (D-1-idx), exactly k per row.
__device__ unsigned long long g_win[(size_t)TK_MAXROWS * TK_CAP];
__device__ int g_cnt[TK_MAXROWS];

struct TKShared {
    unsigned long long cand[TK_CAP];
    int cnt;
    int red;
};

// Order-preserving float->uint key: larger float <=> larger key.
__device__ __forceinline__ unsigned f2k(float f) {
    unsigned b = __float_as_uint(f);
    return b ^ ((unsigned)((int)b >> 31) | 0x80000000u);
}
__device__ __forceinline__ float k2f(unsigned u) {
    unsigned b = u ^ ((u & 0x80000000u) ? 0x80000000u : 0xFFFFFFFFu);
    return __uint_as_float(b);
}

__device__ __forceinline__ void tk_push(TKShared* sm, unsigned u, int idx) {
    int p = atomicAdd(&sm->cnt, 1);
    if (p < TK_CAP)
        sm->cand[p] = ((unsigned long long)u << 32) | (unsigned)(TK_D - 1 - idx);
}

// ===== Block-wide fallback helpers (cold; never taken on N(0,1) data) ======

__device__ void tk_scank(const float* __restrict__ rp,
                         unsigned klo, unsigned khi, TKShared* sm, int tid) {
    #pragma unroll 2
    for (int c = 0; c < TK_NITER; c++) {
        int base = c * TK_CHUNK + tid * 4;
        float4 v = *(const float4*)(rp + base);
        unsigned u0 = f2k(v.x), u1 = f2k(v.y), u2 = f2k(v.z), u3 = f2k(v.w);
        if (u0 > klo && u0 <= khi) tk_push(sm, u0, base + 0);
        if (u1 > klo && u1 <= khi) tk_push(sm, u1, base + 1);
        if (u2 > klo && u2 <= khi) tk_push(sm, u2, base + 2);
        if (u3 > klo && u3 <= khi) tk_push(sm, u3, base + 3);
    }
}

__device__ int tk_count(const float* __restrict__ rp, unsigned a, int b, int mode,
                        TKShared* sm, int tid) {
    __syncthreads();
    if (tid == 0) sm->red = 0;
    __syncthreads();
    int c = 0;
    #pragma unroll 2
    for (int ch = 0; ch < TK_NITER; ch++) {
        int base = ch * TK_CHUNK + tid * 4;
        float4 v = *(const float4*)(rp + base);
        unsigned u0 = f2k(v.x), u1 = f2k(v.y), u2 = f2k(v.z), u3 = f2k(v.w);
        if (mode == 0) {
            c += (int)(u0 > a) + (int)(u1 > a) + (int)(u2 > a) + (int)(u3 > a);
        } else {
            c += (int)(u0 == a && base + 0 <= b) + (int)(u1 == a && base + 1 <= b)
               + (int)(u2 == a && base + 2 <= b) + (int)(u3 == a && base + 3 <= b);
        }
    }
    #pragma unroll
    for (int o = 16; o > 0; o >>= 1) c += __shfl_xor_sync(0xffffffffu, c, o);
    if ((tid & 31) == 0) atomicAdd(&sm->red, c);
    __syncthreads();
    return sm->red;
}

// Block-wide exact selection into the compact buffer.
__device__ void tk_rank_emit(TKShared* sm, int c, int k, int row, int tid) {
    unsigned long long* wrow = g_win + (size_t)row * TK_CAP;
    for (int i = tid; i < c; i += TK_THREADS) {
        unsigned long long K = sm->cand[i];
        int r = 0;
        for (int j = 0; j < c; j++)
            r += (sm->cand[j] > K) ? 1 : 0;
        if (r < k) wrow[r] = K;
    }
}

// Full cold fallback for one row (block-uniform; internal barriers safe).
__device__ void tk_cold_row(const float* __restrict__ rp, TKShared* sm,
                            int cnt, int k, float tlo, int row, int tid) {
    unsigned lo_key = f2k(tlo);
    unsigned hi_key = 0xFFFFFFFFu;      // count(key > hi_key) == 0 < k

    {
        const unsigned krungs[6] = {f2k(1.2f), f2k(0.0f), f2k(-1.2f),
                                    f2k(-2.8f), f2k(-8.0f), 0u};
        int ki = 0;
        while (cnt < k && ki < 6) {
            unsigned k_new = krungs[ki];
            tk_scank(rp, k_new, lo_key, sm, tid);
            __syncthreads();
            cnt = sm->cnt;
            hi_key = lo_key;
            lo_key = k_new;
            ki++;
        }
    }

    if (cnt >= k && cnt <= TK_CAP) {
        tk_rank_emit(sm, cnt, k, row, tid);
        __syncthreads();
        return;
    }

    // Overflow: key-space bisection.
    unsigned lo = lo_key;
    while (hi_key - lo > 1u) {
        unsigned mid = lo + (hi_key - lo) / 2u;
        int cm = tk_count(rp, mid, 0, 0, sm, tid);
        if (cm < k) {
            hi_key = mid;
        } else if (cm <= TK_CAP) {
            __syncthreads();
            if (tid == 0) sm->cnt = 0;
            __syncthreads();
            tk_scank(rp, mid, 0xFFFFFFFFu, sm, tid);
            __syncthreads();
            tk_rank_emit(sm, sm->cnt, k, row, tid);
            __syncthreads();
            return;
        } else {
            lo = mid;
        }
    }

    // Massive-duplicate case: the k-th largest key is exactly hi_key.
    int cgt = tk_count(rp, hi_key, 0, 0, sm, tid);   // strictly greater, < k
    int needed = k - cgt;

    __syncthreads();
    if (tid == 0) sm->cnt = 0;
    __syncthreads();
    tk_scank(rp, hi_key, 0xFFFFFFFFu, sm, tid);
    __syncthreads();
    tk_rank_emit(sm, sm->cnt, k, row, tid);

    int ilo = -1, ihi = TK_D - 1;
    while (ihi - ilo > 1) {
        int im = (ilo + ihi) / 2;
        int ce = tk_count(rp, hi_key, im, 1, sm, tid);
        if (ce >= needed) ihi = im; else ilo = im;
    }
    __syncthreads();
    if (tid == 0) sm->red = cgt;        // slot counter for equal-key emits
    __syncthreads();
    unsigned long long* wrow = g_win + (size_t)row * TK_CAP;
    #pragma unroll 2
    for (int ch = 0; ch < TK_NITER; ch++) {
        int base = ch * TK_CHUNK + tid * 4;
        float4 v = *(const float4*)(rp + base);
        #pragma unroll
        for (int e = 0; e < 4; e++) {
            float f = (e == 0) ? v.x : (e == 1) ? v.y : (e == 2) ? v.z : v.w;
            int idx = base + e;
            if (f2k(f) == hi_key && idx <= ihi) {
                int s = atomicAdd(&sm->red, 1);
                if (s < k)
                    wrow[s] = ((unsigned long long)hi_key << 32)
                            | (unsigned)(TK_D - 1 - idx);
            }
        }
    }
    __syncthreads();
}

// KERNEL A — warp-per-row pure READ stream. 1024 CTAs x 8 warps = 8192 warps,
// one row per warp, ONE wave, ZERO block barriers in the hot path. Each warp
// streams its 64 KB row (mask-deferred collect into a warp-private pool),
// rank-selects warp-collectively, and emits to g_win. Selection tails of
// different warps overlap freely. Out-of-band rows go to a per-CTA bad list
// handled by the block-wide cold machinery after one trailing barrier.
__global__ __launch_bounds__(TK_THREADS, 8)
void tk_select_kernel(const float* __restrict__ in,
                      const int* __restrict__ kptr, int nrows) {
    __shared__ unsigned long long wcand[TK_NWARP][TK_WCAP];
    __shared__ int wcnt[TK_NWARP];
    __shared__ int badlist[TK_NWARP];
    __shared__ int nbad;
    __shared__ TKShared bpool;                 // block-wide fallback pool

    const int tid  = threadIdx.x;
    const int wid  = tid >> 5;
    const int lane = tid & 31;

    int k = kptr ? *kptr : 64;
    if (k < 1) k = 1;
    if (k > TK_CAP) k = TK_CAP;

    if (tid == 0) nbad = 0;
    if (lane == 0) wcnt[wid] = 0;
    __syncthreads();                           // init visible to all warps

    const float TLO = 2.4f;
    const int row = blockIdx.x * TK_NWARP + wid;

    if (row < nrows) {
        const float* rp = in + (size_t)row * TK_D;

        // ---- Stream the row: 128 quads per lane, mask-deferred collect.
        // For iid N(0,1): E[count] ~= 134/row, sd ~= 11.6, so
        // k=64 <= cnt <= 256 at > 10 sigma on both sides.
        #pragma unroll
        for (int o = 0; o < 4; o++) {          // 4 x 32 quads
            unsigned mask = 0;
            #pragma unroll 8
            for (int i = 0; i < 32; i++) {
                int q = o * 32 + i;            // quad id within row
                float4 v = *(const float4*)(rp + (q * 32 + lane) * 4);
                float m = fmaxf(fmaxf(v.x, v.y), fmaxf(v.z, v.w));
                if (m > TLO) mask |= (1u << i);
            }
            while (mask) {                     // rare: revisit flagged quads (L2)
                int i = __ffs(mask) - 1;
                mask &= mask - 1;
                int base = ((o * 32 + i) * 32 + lane) * 4;
                float4 v = *(const float4*)(rp + base);
                #pragma unroll
                for (int e = 0; e < 4; e++) {
                    float f = (e == 0) ? v.x : (e == 1) ? v.y
                            : (e == 2) ? v.z : v.w;
                    if (f > TLO) {
                        int p = atomicAdd(&wcnt[wid], 1);
                        if (p < TK_WCAP)
                            wcand[wid][p] =
                                ((unsigned long long)f2k(f) << 32)
                                | (unsigned)(TK_D - 1 - (base + e));
                    }
                }
            }
        }
        __syncwarp();
        int c = wcnt[wid];

        if (c >= k && c <= TK_WCAP) {
            // Warp-collective exact selection: candidate i wins iff fewer
            // than k candidates have a larger packed key. Keys unique (index
            // embedded) -> exactly k winners. Inner j-loop is lane-uniform ->
            // smem broadcast.
            unsigned long long* wrow = g_win + (size_t)row * TK_CAP;
            for (int i = lane; i < c; i += 32) {
                unsigned long long K = wcand[wid][i];
                int r = 0;
                for (int j = 0; j < c; j++)
                    r += (wcand[wid][j] > K) ? 1 : 0;
                if (r < k) wrow[r] = K;
            }
            if (lane == 0) g_cnt[row] = k;
        } else if (lane == 0) {                // out-of-band -> bad list
            int s = atomicAdd(&nbad, 1);
            badlist[s] = row;
            g_cnt[row] = k;
        }
    }

    // ---- Cold path: block-wide handling of bad rows (empty on N(0,1)). ----
    __syncthreads();
    int nb = nbad;
    for (int bi = 0; bi < nb; bi++) {
        int brow = badlist[bi];
        const float* rp = in + (size_t)brow * TK_D;
        if (tid == 0) bpool.cnt = 0;
        __syncthreads();
        tk_scank(rp, f2k(TLO), 0xFFFFFFFFu, &bpool, tid);   // redo initial scan
        __syncthreads();
        int cnt = bpool.cnt;
        if (cnt >= k && cnt <= TK_CAP) {
            tk_rank_emit(&bpool, cnt, k, brow, tid);
            __syncthreads();
        } else {
            tk_cold_row(rp, &bpool, cnt, k, TLO, brow, tid);
        }
    }
}

// KERNEL B — pure WRITE stream (unchanged; 81.8 us @ ~6.5 TB/s). One CTA per
// row, smem-staged single-touch output: zero image, scatter winners by index,
// stream out with STG.128. No RMW anywhere.
__global__ __launch_bounds__(TK_THREADS)
void tk_expand_kernel(float* __restrict__ out, int nrows) {
    extern __shared__ float srow[];            // TK_D floats = 64 KB
    const int tid = threadIdx.x;
    const int row = blockIdx.x;
    if (row >= nrows) return;

    int n = g_cnt[row];
    if (n > TK_CAP) n = TK_CAP;

    unsigned long long w0 = 0, w1 = 0;
    bool h0 = tid < n, h1 = tid + TK_THREADS < n;
    const unsigned long long* wrow = g_win + (size_t)row * TK_CAP;
    if (h0) w0 = wrow[tid];
    if (h1) w1 = wrow[tid + TK_THREADS];

    #pragma unroll
    for (int i = 0; i < TK_NITER; i++)
        *(float4*)(srow + (i * TK_THREADS + tid) * 4) =
            make_float4(0.f, 0.f, 0.f, 0.f);
    __syncthreads();

    if (h0) {
        int idx = TK_D - 1 - (int)(w0 & 0xFFFFFFFFu);
        srow[idx] = k2f((unsigned)(w0 >> 32));
    }
    if (h1) {
        int idx = TK_D - 1 - (int)(w1 & 0xFFFFFFFFu);
        srow[idx] = k2f((unsigned)(w1 >> 32));
    }
    __syncthreads();

    float* op = out + (size_t)row * TK_D;
    #pragma unroll
    for (int i = 0; i < TK_NITER; i++) {
        int q = (i * TK_THREADS + tid) * 4;
        __stcs((float4*)(op + q), *(const float4*)(srow + q));
    }
}

extern "C" void kernel_launch(void* const* d_in, const int* in_sizes, int n_in,
                              void* d_out, int out_size) {
    const float* in = (const float*)d_in[0];
    const int*   kp = (n_in > 1) ? (const int*)d_in[1] : nullptr;
    int N = in_sizes[0] / TK_D;          // 8192 rows
    if (N > TK_MAXROWS) N = TK_MAXROWS;
    (void)out_size;

    static bool init = false;
    if (!init) {
        cudaFuncSetAttribute(tk_expand_kernel,
                             cudaFuncAttributeMaxDynamicSharedMemorySize,
                             TK_D * (int)sizeof(float));
        init = true;
    }

    // Node 1: warp-per-row pure-read select -> compact winner buffer.
    int gsel = (N + TK_NWARP - 1) / TK_NWARP;  // 1024 CTAs, one wave
    tk_select_kernel<<<gsel, TK_THREADS>>>(in, kp, N);

    // Node 2: pure-write zero+scatter via smem staging (single-touch output).
    tk_expand_kernel<<<N, TK_THREADS, TK_D * sizeof(float)>>>((float*)d_out, N);
}

// round 15
// speedup vs baseline: 1.1164x; 1.1164x over previous
#include <cuda_runtime.h>

#define TK_D       16384
#define TK_THREADS 256
#define TK_CHUNK   (TK_THREADS * 4)          // 1024 elements per iteration
#define TK_NITER   (TK_D / TK_CHUNK)         // 16
#define TK_CAP     512
#define TK_GRID    1184                      // 148 SMs x 8 CTAs: one wave
#define TK_NPOOL   3

struct TKShared {
    unsigned long long cand[TK_CAP];   // (ordered_key << 32) | (D-1-idx)
    int cnt;
    int red;
};

// Order-preserving float->uint key: larger float <=> larger key.
__device__ __forceinline__ unsigned f2k(float f) {
    unsigned b = __float_as_uint(f);
    return b ^ ((unsigned)((int)b >> 31) | 0x80000000u);
}
__device__ __forceinline__ float k2f(unsigned u) {
    unsigned b = u ^ ((u & 0x80000000u) ? 0x80000000u : 0xFFFFFFFFu);
    return __uint_as_float(b);
}

__device__ __forceinline__ void tk_push(TKShared* sm, unsigned u, int idx) {
    int p = atomicAdd(&sm->cnt, 1);
    if (p < TK_CAP)
        sm->cand[p] = ((unsigned long long)u << 32) | (unsigned)(TK_D - 1 - idx);
}

// Deferred candidate collection: revisit only flagged chunks (~0.5 per thread,
// L2-resident because the stream used default caching).
__device__ void tk_collect(const float* __restrict__ rp, float tlo, unsigned mask,
                           TKShared* sm, int tid) {
    while (mask) {
        int c = __ffs(mask) - 1;
        mask &= mask - 1;
        int base = c * TK_CHUNK + tid * 4;
        float4 v = *(const float4*)(rp + base);
        if (v.x > tlo) tk_push(sm, f2k(v.x), base + 0);
        if (v.y > tlo) tk_push(sm, f2k(v.y), base + 1);
        if (v.z > tlo) tk_push(sm, f2k(v.z), base + 2);
        if (v.w > tlo) tk_push(sm, f2k(v.w), base + 3);
    }
}

// Key-space scan: push keys in (klo, khi]. Fallback paths only.
__device__ void tk_scank(const float* __restrict__ rp,
                         unsigned klo, unsigned khi, TKShared* sm, int tid) {
    #pragma unroll 2
    for (int c = 0; c < TK_NITER; c++) {
        int base = c * TK_CHUNK + tid * 4;
        float4 v = *(const float4*)(rp + base);
        unsigned u0 = f2k(v.x), u1 = f2k(v.y), u2 = f2k(v.z), u3 = f2k(v.w);
        if (u0 > klo && u0 <= khi) tk_push(sm, u0, base + 0);
        if (u1 > klo && u1 <= khi) tk_push(sm, u1, base + 1);
        if (u2 > klo && u2 <= khi) tk_push(sm, u2, base + 2);
        if (u3 > klo && u3 <= khi) tk_push(sm, u3, base + 3);
    }
}

// mode 0: count keys > a ; mode 1: count (key == a && idx <= b). Block-wide.
__device__ int tk_count(const float* __restrict__ rp, unsigned a, int b, int mode,
                        TKShared* sm, int tid) {
    __syncthreads();
    if (tid == 0) sm->red = 0;
    __syncthreads();
    int c = 0;
    #pragma unroll 2
    for (int ch = 0; ch < TK_NITER; ch++) {
        int base = ch * TK_CHUNK + tid * 4;
        float4 v = *(const float4*)(rp + base);
        unsigned u0 = f2k(v.x), u1 = f2k(v.y), u2 = f2k(v.z), u3 = f2k(v.w);
        if (mode == 0) {
            c += (int)(u0 > a) + (int)(u1 > a) + (int)(u2 > a) + (int)(u3 > a);
        } else {
            c += (int)(u0 == a && base + 0 <= b) + (int)(u1 == a && base + 1 <= b)
               + (int)(u2 == a && base + 2 <= b) + (int)(u3 == a && base + 3 <= b);
        }
    }
    #pragma unroll
    for (int o = 16; o > 0; o >>= 1) c += __shfl_xor_sync(0xffffffffu, c, o);
    if ((tid & 31) == 0) atomicAdd(&sm->red, c);
    __syncthreads();
    return sm->red;
}

// Exact selection: candidate i wins iff fewer than k candidates have a larger
// packed key. Keys unique (index embedded) -> exactly min(c,k) winners.
// Inner reads are warp-uniform -> smem broadcast (conflict-free). Only threads
// with tid < c do work; the rest fall through to the next row's stream.
__device__ void tk_rank_scatter(TKShared* sm, int c, int k, float* __restrict__ op, int tid) {
    for (int i = tid; i < c; i += TK_THREADS) {
        unsigned long long K = sm->cand[i];
        int r = 0;
        for (int j = 0; j < c; j++)
            r += (sm->cand[j] > K) ? 1 : 0;
        if (r < k) {
            unsigned u = (unsigned)(K >> 32);
            int idx = TK_D - 1 - (int)(K & 0xFFFFFFFFu);
            op[idx] = k2f(u);
        }
    }
}

// Cold fallback for one row (never taken on N(0,1) data). Block-uniform
// control flow; internal __syncthreads are safe. Ends with a barrier so the
// 3-pool rotation invariants hold trivially on this path.
__device__ void tk_cold_row(const float* __restrict__ rp, float* __restrict__ op,
                            TKShared* sm, int cnt, int k, float tlo, int tid) {
    unsigned lo_key = f2k(tlo);
    unsigned hi_key = 0xFFFFFFFFu;      // count(key > hi_key) == 0 < k

    // Undershoot ladder in key space.
    {
        const unsigned krungs[6] = {f2k(1.2f), f2k(0.0f), f2k(-1.2f),
                                    f2k(-2.8f), f2k(-8.0f), 0u};
        int ki = 0;
        while (cnt < k && ki < 6) {
            unsigned k_new = krungs[ki];
            tk_scank(rp, k_new, lo_key, sm, tid);
            __syncthreads();
            cnt = sm->cnt;
            hi_key = lo_key;
            lo_key = k_new;
            ki++;
        }
    }

    if (cnt >= k && cnt <= TK_CAP) {
        tk_rank_scatter(sm, cnt, k, op, tid);
        __syncthreads();
        return;
    }

    // Overflow: key-space bisection.
    // Invariants: count(key > lo_key) >= cnt > CAP >= k ; count(key > hi_key) < k.
    unsigned lo = lo_key;
    while (hi_key - lo > 1u) {
        unsigned mid = lo + (hi_key - lo) / 2u;
        int cm = tk_count(rp, mid, 0, 0, sm, tid);
        if (cm < k) {
            hi_key = mid;
        } else if (cm <= TK_CAP) {
            __syncthreads();
            if (tid == 0) sm->cnt = 0;
            __syncthreads();
            tk_scank(rp, mid, 0xFFFFFFFFu, sm, tid);
            __syncthreads();
            tk_rank_scatter(sm, sm->cnt, k, op, tid);
            __syncthreads();
            return;
        } else {
            lo = mid;
        }
    }

    // Massive-duplicate case: the k-th largest key is exactly hi_key.
    int cgt = tk_count(rp, hi_key, 0, 0, sm, tid);   // strictly greater, < k
    int needed = k - cgt;

    // Scatter all strict winners (cgt < k <= CAP: they all fit & all win).
    __syncthreads();
    if (tid == 0) sm->cnt = 0;
    __syncthreads();
    tk_scank(rp, hi_key, 0xFFFFFFFFu, sm, tid);
    __syncthreads();
    tk_rank_scatter(sm, sm->cnt, k, op, tid);

    // Among keys == hi_key, take the `needed` smallest indices: bisect cutoff.
    int ilo = -1, ihi = TK_D - 1;
    while (ihi - ilo > 1) {
        int im = (ilo + ihi) / 2;
        int ce = tk_count(rp, hi_key, im, 1, sm, tid);
        if (ce >= needed) ihi = im; else ilo = im;
    }
    __syncthreads();
    #pragma unroll 2
    for (int ch = 0; ch < TK_NITER; ch++) {
        int base = ch * TK_CHUNK + tid * 4;
        float4 v = *(const float4*)(rp + base);
        if (f2k(v.x) == hi_key && base + 0 <= ihi) op[base + 0] = v.x;
        if (f2k(v.y) == hi_key && base + 1 <= ihi) op[base + 1] = v.y;
        if (f2k(v.z) == hi_key && base + 2 <= ihi) op[base + 2] = v.z;
        if (f2k(v.w) == hi_key && base + 3 <= ihi) op[base + 3] = v.w;
    }
    __syncthreads();
}

// Output rows are pre-zeroed by the memset graph node; this kernel only reads
// the input and scatters the k winners. PERSISTENT CTAs with a 3-pool rotation
// and ONE barrier per row:
//   - row r uses pool r%3; tid0 resets pool (r+1)%3 BEFORE the barrier. That
//     pool's last user was row r-2, whose selection completed before row r-1's
//     barrier (every thread finishes selection of row q before streaming row
//     q+1 and arriving at row q+1's barrier), so the reset is race-free. The
//     barrier then publishes the reset before row r+1's pushes.
//   - Fast-path selection has no trailing barrier: threads with tid >= cnt
//     start row r+1's loads immediately, hiding the select tail. Pool r%3 is
//     reused only at row r+3.
__global__ __launch_bounds__(TK_THREADS, 8)
void TopKActivation_68324339745162_kernel(const float* __restrict__ in,
                                          const int* __restrict__ kptr,
                                          float* __restrict__ out,
                                          int nrows) {
    __shared__ TKShared pool[TK_NPOOL];
    const int tid = threadIdx.x;

    int k = kptr ? *kptr : 64;
    if (k < 1) k = 1;
    if (k > TK_CAP) k = TK_CAP;

    if (tid == 0) {
        pool[0].cnt = 0; pool[1].cnt = 0; pool[2].cnt = 0;
    }
    __syncthreads();

    const float TLO = 2.4f;
    int p = 0;

    for (int row = blockIdx.x; row < nrows; row += gridDim.x) {
        const float* rp = in + (size_t)row * TK_D;
        float*       op = out + (size_t)row * TK_D;
        TKShared* sm = &pool[p];

        // ---- Stream the row: flag quads with x > 2.4. For iid N(0,1),
        // E[count] ~= 134/row, sd ~= 11.6: 64 <= cnt <= 512 at >20 sigma.
        unsigned mask = 0;
        #pragma unroll 4
        for (int c = 0; c < TK_NITER; c++) {
            int base = c * TK_CHUNK + tid * 4;
            float4 v = *(const float4*)(rp + base);
            float m = fmaxf(fmaxf(v.x, v.y), fmaxf(v.z, v.w));
            if (m > TLO) mask |= (1u << c);
        }
        if (mask) tk_collect(rp, TLO, mask, sm, tid);

        // Reset NEXT row's pool before the barrier (see rotation proof above).
        if (tid == 0) {
            int np = p + 1; if (np == TK_NPOOL) np = 0;
            pool[np].cnt = 0;
        }
        __syncthreads();                 // pushes done + reset published
        int cnt = sm->cnt;

        if (cnt >= k && cnt <= TK_CAP) {
            // Fast path: exact rank selection, fused scatter. No trailing
            // barrier — idle threads flow straight into the next row's loads.
            tk_rank_scatter(sm, cnt, k, op, tid);
        } else {
            tk_cold_row(rp, op, sm, cnt, k, TLO, tid);
        }
        p++; if (p == TK_NPOOL) p = 0;
    }
}

extern "C" void kernel_launch(void* const* d_in, const int* in_sizes, int n_in,
                              void* d_out, int out_size) {
    const float* in = (const float*)d_in[0];
    const int*   kp = (n_in > 1) ? (const int*)d_in[1] : nullptr;
    int N = in_sizes[0] / TK_D;          // 8192 rows

    // Node 1: pure-write stream — zero the whole output (~6.5 TB/s).
    cudaMemsetAsync(d_out, 0, (size_t)out_size * sizeof(float), 0);

    // Node 2: pure-read stream — persistent CTAs, select + fused scatter.
    int grid = (N < TK_GRID) ? N : TK_GRID;
    TopKActivation_68324339745162_kernel<<<grid, TK_THREADS>>>(in, kp, (float*)d_out, N);
}

// round 16
// speedup vs baseline: 1.1184x; 1.0017x over previous
#include <cuda_runtime.h>

#define TK_D       16384
#define TK_THREADS 256
#define TK_CHUNK   (TK_THREADS * 4)          // 1024 elements per iteration
#define TK_NITER   (TK_D / TK_CHUNK)         // 16
#define TK_CAP     512
#define TK_GRID    1024                      // 8192 rows / 1024 = exactly 8
                                             // rows per CTA: zero imbalance,
                                             // still a single wave (cap 1184)
#define TK_NPOOL   3

struct TKShared {
    unsigned long long cand[TK_CAP];   // (ordered_key << 32) | (D-1-idx)
    int cnt;
    int red;
};

// Order-preserving float->uint key: larger float <=> larger key.
__device__ __forceinline__ unsigned f2k(float f) {
    unsigned b = __float_as_uint(f);
    return b ^ ((unsigned)((int)b >> 31) | 0x80000000u);
}
__device__ __forceinline__ float k2f(unsigned u) {
    unsigned b = u ^ ((u & 0x80000000u) ? 0x80000000u : 0xFFFFFFFFu);
    return __uint_as_float(b);
}

__device__ __forceinline__ void tk_push(TKShared* sm, unsigned u, int idx) {
    int p = atomicAdd(&sm->cnt, 1);
    if (p < TK_CAP)
        sm->cand[p] = ((unsigned long long)u << 32) | (unsigned)(TK_D - 1 - idx);
}

// Deferred candidate collection: revisit only flagged chunks (~0.5 per thread,
// L2-resident because the stream used default caching).
__device__ void tk_collect(const float* __restrict__ rp, float tlo, unsigned mask,
                           TKShared* sm, int tid) {
    while (mask) {
        int c = __ffs(mask) - 1;
        mask &= mask - 1;
        int base = c * TK_CHUNK + tid * 4;
        float4 v = *(const float4*)(rp + base);
        if (v.x > tlo) tk_push(sm, f2k(v.x), base + 0);
        if (v.y > tlo) tk_push(sm, f2k(v.y), base + 1);
        if (v.z > tlo) tk_push(sm, f2k(v.z), base + 2);
        if (v.w > tlo) tk_push(sm, f2k(v.w), base + 3);
    }
}

// Key-space scan: push keys in (klo, khi]. Fallback paths only.
__device__ void tk_scank(const float* __restrict__ rp,
                         unsigned klo, unsigned khi, TKShared* sm, int tid) {
    #pragma unroll 2
    for (int c = 0; c < TK_NITER; c++) {
        int base = c * TK_CHUNK + tid * 4;
        float4 v = *(const float4*)(rp + base);
        unsigned u0 = f2k(v.x), u1 = f2k(v.y), u2 = f2k(v.z), u3 = f2k(v.w);
        if (u0 > klo && u0 <= khi) tk_push(sm, u0, base + 0);
        if (u1 > klo && u1 <= khi) tk_push(sm, u1, base + 1);
        if (u2 > klo && u2 <= khi) tk_push(sm, u2, base + 2);
        if (u3 > klo && u3 <= khi) tk_push(sm, u3, base + 3);
    }
}

// mode 0: count keys > a ; mode 1: count (key == a && idx <= b). Block-wide.
__device__ int tk_count(const float* __restrict__ rp, unsigned a, int b, int mode,
                        TKShared* sm, int tid) {
    __syncthreads();
    if (tid == 0) sm->red = 0;
    __syncthreads();
    int c = 0;
    #pragma unroll 2
    for (int ch = 0; ch < TK_NITER; ch++) {
        int base = ch * TK_CHUNK + tid * 4;
        float4 v = *(const float4*)(rp + base);
        unsigned u0 = f2k(v.x), u1 = f2k(v.y), u2 = f2k(v.z), u3 = f2k(v.w);
        if (mode == 0) {
            c += (int)(u0 > a) + (int)(u1 > a) + (int)(u2 > a) + (int)(u3 > a);
        } else {
            c += (int)(u0 == a && base + 0 <= b) + (int)(u1 == a && base + 1 <= b)
               + (int)(u2 == a && base + 2 <= b) + (int)(u3 == a && base + 3 <= b);
        }
    }
    #pragma unroll
    for (int o = 16; o > 0; o >>= 1) c += __shfl_xor_sync(0xffffffffu, c, o);
    if ((tid & 31) == 0) atomicAdd(&sm->red, c);
    __syncthreads();
    return sm->red;
}

// Exact selection: candidate i wins iff fewer than k candidates have a larger
// packed key. Keys unique (index embedded) -> exactly min(c,k) winners.
// Inner reads are warp-uniform -> smem broadcast (conflict-free). Only threads
// with tid < c do work; the rest fall through to the next row's stream.
__device__ void tk_rank_scatter(TKShared* sm, int c, int k, float* __restrict__ op, int tid) {
    for (int i = tid; i < c; i += TK_THREADS) {
        unsigned long long K = sm->cand[i];
        int r = 0;
        for (int j = 0; j < c; j++)
            r += (sm->cand[j] > K) ? 1 : 0;
        if (r < k) {
            unsigned u = (unsigned)(K >> 32);
            int idx = TK_D - 1 - (int)(K & 0xFFFFFFFFu);
            op[idx] = k2f(u);
        }
    }
}

// Cold fallback for one row (never taken on N(0,1) data). Block-uniform
// control flow; internal __syncthreads are safe. Ends with a barrier so the
// 3-pool rotation invariants hold trivially on this path.
__device__ void tk_cold_row(const float* __restrict__ rp, float* __restrict__ op,
                            TKShared* sm, int cnt, int k, float tlo, int tid) {
    unsigned lo_key = f2k(tlo);
    unsigned hi_key = 0xFFFFFFFFu;      // count(key > hi_key) == 0 < k

    // Undershoot ladder in key space.
    {
        const unsigned krungs[6] = {f2k(1.2f), f2k(0.0f), f2k(-1.2f),
                                    f2k(-2.8f), f2k(-8.0f), 0u};
        int ki = 0;
        while (cnt < k && ki < 6) {
            unsigned k_new = krungs[ki];
            tk_scank(rp, k_new, lo_key, sm, tid);
            __syncthreads();
            cnt = sm->cnt;
            hi_key = lo_key;
            lo_key = k_new;
            ki++;
        }
    }

    if (cnt >= k && cnt <= TK_CAP) {
        tk_rank_scatter(sm, cnt, k, op, tid);
        __syncthreads();
        return;
    }

    // Overflow: key-space bisection.
    // Invariants: count(key > lo_key) >= cnt > CAP >= k ; count(key > hi_key) < k.
    unsigned lo = lo_key;
    while (hi_key - lo > 1u) {
        unsigned mid = lo + (hi_key - lo) / 2u;
        int cm = tk_count(rp, mid, 0, 0, sm, tid);
        if (cm < k) {
            hi_key = mid;
        } else if (cm <= TK_CAP) {
            __syncthreads();
            if (tid == 0) sm->cnt = 0;
            __syncthreads();
            tk_scank(rp, mid, 0xFFFFFFFFu, sm, tid);
            __syncthreads();
            tk_rank_scatter(sm, sm->cnt, k, op, tid);
            __syncthreads();
            return;
        } else {
            lo = mid;
        }
    }

    // Massive-duplicate case: the k-th largest key is exactly hi_key.
    int cgt = tk_count(rp, hi_key, 0, 0, sm, tid);   // strictly greater, < k
    int needed = k - cgt;

    // Scatter all strict winners (cgt < k <= CAP: they all fit & all win).
    __syncthreads();
    if (tid == 0) sm->cnt = 0;
    __syncthreads();
    tk_scank(rp, hi_key, 0xFFFFFFFFu, sm, tid);
    __syncthreads();
    tk_rank_scatter(sm, sm->cnt, k, op, tid);

    // Among keys == hi_key, take the `needed` smallest indices: bisect cutoff.
    int ilo = -1, ihi = TK_D - 1;
    while (ihi - ilo > 1) {
        int im = (ilo + ihi) / 2;
        int ce = tk_count(rp, hi_key, im, 1, sm, tid);
        if (ce >= needed) ihi = im; else ilo = im;
    }
    __syncthreads();
    #pragma unroll 2
    for (int ch = 0; ch < TK_NITER; ch++) {
        int base = ch * TK_CHUNK + tid * 4;
        float4 v = *(const float4*)(rp + base);
        if (f2k(v.x) == hi_key && base + 0 <= ihi) op[base + 0] = v.x;
        if (f2k(v.y) == hi_key && base + 1 <= ihi) op[base + 1] = v.y;
        if (f2k(v.z) == hi_key && base + 2 <= ihi) op[base + 2] = v.z;
        if (f2k(v.w) == hi_key && base + 3 <= ihi) op[base + 3] = v.w;
    }
    __syncthreads();
}

// Output rows are pre-zeroed by the memset graph node; this kernel only reads
// the input and scatters the k winners. PERSISTENT CTAs (exactly 8 rows each
// at N=8192: zero CTA-level imbalance) with a 3-pool rotation and ONE barrier
// per row:
//   - row r uses pool r%3; tid0 resets pool (r+1)%3 BEFORE the barrier. That
//     pool's last user was row r-2, whose selection completed before row r-1's
//     barrier (every thread finishes selection of row q before streaming row
//     q+1 and arriving at row q+1's barrier), so the reset is race-free. The
//     barrier then publishes the reset before row r+1's pushes.
//   - Fast-path selection has no trailing barrier: threads with tid >= cnt
//     start row r+1's loads immediately, hiding the select tail. Pool r%3 is
//     reused only at row r+3.
__global__ __launch_bounds__(TK_THREADS, 8)
void TopKActivation_68324339745162_kernel(const float* __restrict__ in,
                                          const int* __restrict__ kptr,
                                          float* __restrict__ out,
                                          int nrows) {
    __shared__ TKShared pool[TK_NPOOL];
    const int tid = threadIdx.x;

    int k = kptr ? *kptr : 64;
    if (k < 1) k = 1;
    if (k > TK_CAP) k = TK_CAP;

    if (tid == 0) {
        pool[0].cnt = 0; pool[1].cnt = 0; pool[2].cnt = 0;
    }
    __syncthreads();

    const float TLO = 2.4f;
    int p = 0;

    for (int row = blockIdx.x; row < nrows; row += gridDim.x) {
        const float* rp = in + (size_t)row * TK_D;
        float*       op = out + (size_t)row * TK_D;
        TKShared* sm = &pool[p];

        // ---- Stream the row: flag quads with x > 2.4. For iid N(0,1),
        // E[count] ~= 134/row, sd ~= 11.6: 64 <= cnt <= 512 at >20 sigma.
        unsigned mask = 0;
        #pragma unroll 4
        for (int c = 0; c < TK_NITER; c++) {
            int base = c * TK_CHUNK + tid * 4;
            float4 v = *(const float4*)(rp + base);
            float m = fmaxf(fmaxf(v.x, v.y), fmaxf(v.z, v.w));
            if (m > TLO) mask |= (1u << c);
        }
        if (mask) tk_collect(rp, TLO, mask, sm, tid);

        // Reset NEXT row's pool before the barrier (see rotation proof above).
        if (tid == 0) {
            int np = p + 1; if (np == TK_NPOOL) np = 0;
            pool[np].cnt = 0;
        }
        __syncthreads();                 // pushes done + reset published
        int cnt = sm->cnt;

        if (cnt >= k && cnt <= TK_CAP) {
            // Fast path: exact rank selection, fused scatter. No trailing
            // barrier — idle threads flow straight into the next row's loads.
            tk_rank_scatter(sm, cnt, k, op, tid);
        } else {
            tk_cold_row(rp, op, sm, cnt, k, TLO, tid);
        }
        p++; if (p == TK_NPOOL) p = 0;
    }
}

extern "C" void kernel_launch(void* const* d_in, const int* in_sizes, int n_in,
                              void* d_out, int out_size) {
    const float* in = (const float*)d_in[0];
    const int*   kp = (n_in > 1) ? (const int*)d_in[1] : nullptr;
    int N = in_sizes[0] / TK_D;          // 8192 rows

    // Node 1: pure-write stream — zero the whole output (~6.5 TB/s).
    cudaMemsetAsync(d_out, 0, (size_t)out_size * sizeof(float), 0);

    // Node 2: pure-read stream — persistent CTAs (8 rows each, balanced),
    // select + fused scatter.
    int grid = (N < TK_GRID) ? N : TK_GRID;
    TopKActivation_68324339745162_kernel<<<grid, TK_THREADS>>>(in, kp, (float*)d_out, N);
}